// round 7
// baseline (speedup 1.0000x reference)
#include <cuda_runtime.h>
#include <math.h>

#define N_NODES 512
#define BATCH   128
#define UNITS   64
#define M_DIFF  5
#define E_EDGES 8192
#define T_INS   12
#define T_OUTS  12
#define NB      (N_NODES*BATCH)   // 65536
#define C0      65
#define C1      128
#define SL0     72                // layer0 per-m slice stride (pad 65->72)
#define SL1     128
#define LDA0    368               // 5*72 = 360, padded to 368 (mult of 16)
#define LDA1    640               // 5*128
#define K0NKT   23                // 368/16
#define K1NKT   40                // 640/16

// ---------------- scratch (static __device__, zero-init, no allocation) ----
__device__ float g_A[N_NODES*N_NODES];
__device__ float g_invrow[N_NODES];
__device__ float g_invcol[N_NODES];
__device__ int   g_cnt1[N_NODES], g_cnt2[N_NODES];
__device__ int   g_ptr1[N_NODES+1], g_ptr2[N_NODES+1];
__device__ int   g_cur1[N_NODES], g_cur2[N_NODES];
__device__ int   g_col1[E_EDGES], g_col2[E_EDGES];
__device__ float g_val1[E_EDGES], g_val2[E_EDGES];
__device__ float g_XG0[NB*LDA0];   // gate0 stack  [nb, m*72+c], pad cols stay zero
__device__ float g_XC0[NB*LDA0];   // cand0 stack
__device__ float g_XG1[NB*LDA1];   // gate1 stack  [nb, m*128+c]
__device__ float g_XC1[NB*LDA1];   // cand1 stack
__device__ float g_u  [NB*UNITS];  // update gate
__device__ float g_h0 [NB*UNITS];
__device__ float g_h1 [NB*UNITS];
__device__ float g_Wg0[LDA0*2*UNITS];  // permuted weights, k = m*SL+c, pads zero
__device__ float g_Wc0[LDA0*UNITS];
__device__ float g_Wg1[LDA1*2*UNITS];
__device__ float g_Wc1[LDA1*UNITS];

// ---------------- setup kernels ----------------
__global__ void zero_setup_k() {
    int idx = blockIdx.x * 256 + threadIdx.x;
    if (idx < N_NODES*N_NODES) g_A[idx] = 0.f;
    if (idx < N_NODES) { g_cnt1[idx]=0; g_cnt2[idx]=0; g_cur1[idx]=0; g_cur2[idx]=0; }
}
// zero recurrent state + the x0 h-slices that are read before first write
__global__ void zero_state_k() {
    int idx = blockIdx.x * 256 + threadIdx.x;
    if (idx >= NB*128) return;
    int nb = idx >> 7, cc = idx & 127;
    g_XG1[nb*LDA1 + cc] = 0.f;
    if (cc < 64) {
        g_h0[nb*64 + cc] = 0.f;
        g_h1[nb*64 + cc] = 0.f;
        g_XG0[nb*LDA0 + 1 + cc] = 0.f;
    }
}
__global__ void zgo_k() {   // decoder go symbol: zero x-input column of layer0 stacks
    int idx = blockIdx.x * 256 + threadIdx.x;
    if (idx < NB) { g_XG0[idx*LDA0] = 0.f; g_XC0[idx*LDA0] = 0.f; }
}
__global__ void scatter_k(const int* __restrict__ ei, const float* __restrict__ ea) {
    int e = blockIdx.x * 256 + threadIdx.x;
    if (e < E_EDGES) atomicAdd(&g_A[ei[e]*N_NODES + ei[E_EDGES+e]], ea[e]);
}
__global__ void rowinv_k() {
    __shared__ float sh[256];
    int r = blockIdx.x;
    float s = 0.f;
    for (int j = threadIdx.x; j < N_NODES; j += 256) s += g_A[r*N_NODES + j];
    sh[threadIdx.x] = s; __syncthreads();
    for (int o = 128; o > 0; o >>= 1) {
        if (threadIdx.x < o) sh[threadIdx.x] += sh[threadIdx.x + o];
        __syncthreads();
    }
    if (threadIdx.x == 0) { float d = sh[0]; g_invrow[r] = d > 0.f ? 1.f/d : 0.f; }
}
__global__ void colinv_k() {
    int c = blockIdx.x * 256 + threadIdx.x;
    if (c < N_NODES) {
        float s = 0.f;
        for (int i = 0; i < N_NODES; i++) s += g_A[i*N_NODES + c];
        g_invcol[c] = s > 0.f ? 1.f/s : 0.f;
    }
}
__global__ void count_k() {
    int idx = blockIdx.x * 256 + threadIdx.x;
    if (idx >= N_NODES*N_NODES) return;
    if (g_A[idx] != 0.f) {
        int i = idx / N_NODES, j = idx - i*N_NODES;
        atomicAdd(&g_cnt2[i], 1);
        atomicAdd(&g_cnt1[j], 1);
    }
}
__global__ void scan_k() {
    if (threadIdx.x == 0) {
        int s = 0;
        for (int i = 0; i < N_NODES; i++) { g_ptr1[i] = s; s += g_cnt1[i]; }
        g_ptr1[N_NODES] = s;
    }
    if (threadIdx.x == 1) {
        int s = 0;
        for (int i = 0; i < N_NODES; i++) { g_ptr2[i] = s; s += g_cnt2[i]; }
        g_ptr2[N_NODES] = s;
    }
}
__global__ void fill_k() {
    int idx = blockIdx.x * 256 + threadIdx.x;
    if (idx >= N_NODES*N_NODES) return;
    float a = g_A[idx];
    if (a != 0.f) {
        int i = idx / N_NODES, j = idx - i*N_NODES;
        int p2 = atomicAdd(&g_cur2[i], 1);
        int o2 = g_ptr2[i] + p2;
        g_col2[o2] = j; g_val2[o2] = a * g_invcol[j];
        int p1 = atomicAdd(&g_cur1[j], 1);
        int o1 = g_ptr1[j] + p1;
        g_col1[o1] = i; g_val1[o1] = a * g_invrow[i];
    }
}
// permute + Chebyshev-fold:  dest row (m*SL + c) gets
//   m=0: W0 - W2 - W4 ; m=1: W1 ; m=2: 2*W2 ; m=3: W3 ; m=4: 2*W4
__global__ void permW_k(const float* __restrict__ W, int dsel, int C, int SL, int OUT) {
    int idx = blockIdx.x * 256 + threadIdx.x;
    int tot = M_DIFF * C * OUT;
    if (idx >= tot) return;
    int o = idx % OUT, rc = idx / OUT;
    int m = rc / C, c = rc - m*C;
    float v;
    if (m == 0)
        v = W[(c*M_DIFF+0)*OUT+o] - W[(c*M_DIFF+2)*OUT+o] - W[(c*M_DIFF+4)*OUT+o];
    else if (m == 2) v = 2.f * W[(c*M_DIFF+2)*OUT+o];
    else if (m == 4) v = 2.f * W[(c*M_DIFF+4)*OUT+o];
    else             v = W[(c*M_DIFF+m)*OUT+o];
    float* dst = (dsel==0) ? g_Wg0 : (dsel==1) ? g_Wc0 : (dsel==2) ? g_Wg1 : g_Wc1;
    dst[(m*SL + c)*OUT + o] = v;
}

// ---------------- per-step kernels ----------------
__global__ void in_k(const float* __restrict__ hist_t) {
    int idx = blockIdx.x * 256 + threadIdx.x;
    if (idx >= NB) return;
    int b = idx >> 9, n = idx & 511;
    float v = hist_t[idx];
    int nb = n*BATCH + b;
    g_XG0[nb*LDA0] = v;
    g_XC0[nb*LDA0] = v;
}

// ---- fused two-phase SMEM-tile SpMM.
// One block owns a [512 x TW] column tile of (batch b, cols cbase..cbase+TW).
// phase0: x1 = S @ x0 (x0 from SMEM buf0) -> global slice(1+2*sup) AND SMEM buf1
// phase1: x2 = S @ x1 (x1 from SMEM buf1) -> global slice(2+2*sup)
// Chebyshev scaling is folded into the GEMM weights, so plain S@x both phases.
template<int LAY>
__global__ __launch_bounds__(512) void spmm_fused_k(int sel) {
    constexpr int TW  = LAY ? 32 : 36;
    constexpr int SL  = LAY ? SL1 : SL0;
    constexpr int LDA = LAY ? LDA1 : LDA0;
    constexpr int SH  = LAY ? 2 : 1;        // tiles per batch = 1<<SH
    constexpr int TW4 = TW / 4;
    extern __shared__ float sm[];           // [2][512*TW]
    float* s0 = sm;
    float* s1 = sm + 512*TW;
    float* XS = LAY ? (sel ? g_XC1 : g_XG1) : (sel ? g_XC0 : g_XG0);
    const int sup = blockIdx.z;
    const int b     = blockIdx.x >> SH;
    const int cbase = (blockIdx.x & ((1<<SH)-1)) * TW;
    const int*   rp = sup ? g_ptr2 : g_ptr1;
    const int*   ci = sup ? g_col2 : g_col1;
    const float* cv = sup ? g_val2 : g_val1;
    const int tid = threadIdx.x;

    // load x0 tile (slice 0)
    for (int idx = tid; idx < 512*TW4; idx += 512) {
        int n = idx / TW4, w = idx - n*TW4;
        *(float4*)&s0[n*TW + w*4] =
            *(const float4*)&XS[(n*BATCH + b)*LDA + cbase + w*4];
    }
    __syncthreads();

    int c, stream, nstep; bool active;
    if (LAY) { c = tid & 31; stream = tid >> 5; nstep = 16; active = true; }
    else     { c = tid % 36; stream = tid / 36; nstep = 14; active = (tid < 504); }

    const int oo0 = (1 + 2*sup)*SL + cbase;
    if (active) {
        for (int n = stream; n < N_NODES; n += nstep) {
            int e0 = rp[n], e1 = rp[n+1];
            float a0=0.f, a1=0.f, a2=0.f, a3=0.f;
            int e = e0;
            for (; e + 4 <= e1; e += 4) {
                a0 += cv[e]   * s0[ci[e]*TW   + c];
                a1 += cv[e+1] * s0[ci[e+1]*TW + c];
                a2 += cv[e+2] * s0[ci[e+2]*TW + c];
                a3 += cv[e+3] * s0[ci[e+3]*TW + c];
            }
            for (; e < e1; e++) a0 += cv[e] * s0[ci[e]*TW + c];
            float r = (a0+a1)+(a2+a3);
            s1[n*TW + c] = r;
            XS[(n*BATCH + b)*LDA + oo0 + c] = r;
        }
    }
    __syncthreads();

    const int oo1 = (2 + 2*sup)*SL + cbase;
    if (active) {
        for (int n = stream; n < N_NODES; n += nstep) {
            int e0 = rp[n], e1 = rp[n+1];
            float a0=0.f, a1=0.f, a2=0.f, a3=0.f;
            int e = e0;
            for (; e + 4 <= e1; e += 4) {
                a0 += cv[e]   * s1[ci[e]*TW   + c];
                a1 += cv[e+1] * s1[ci[e+1]*TW + c];
                a2 += cv[e+2] * s1[ci[e+2]*TW + c];
                a3 += cv[e+3] * s1[ci[e+3]*TW + c];
            }
            for (; e < e1; e++) a0 += cv[e] * s1[ci[e]*TW + c];
            XS[(n*BATCH + b)*LDA + oo1 + c] = (a0+a1)+(a2+a3);
        }
    }
}

// ---------------- TF32 tensor-core GEMM with fused DCGRU epilogues ----------
__device__ __forceinline__ unsigned f2tf(float f) {
    unsigned u; asm("cvt.rna.tf32.f32 %0, %1;" : "=r"(u) : "f"(f)); return u;
}
__device__ __forceinline__ float4 tf4(float4 v) {
    float4 r;
    r.x = __uint_as_float(f2tf(v.x)); r.y = __uint_as_float(f2tf(v.y));
    r.z = __uint_as_float(f2tf(v.z)); r.w = __uint_as_float(f2tf(v.w));
    return r;
}
// EPI: 0=gate0 (A=XG0, sigmoid, writes r*h0->XC0, u->g_u)
//      1=cand0 (A=XC0, tanh, h0n -> g_h0, XG0, XG1[0:64), XC1[0:64))
//      2=gate1 (A=XG1, sigmoid, writes r*h1->XC1[64:), u->g_u)
//      3=cand1 (A=XC1, tanh, h1n -> g_h1, XG1[64:))
template<int EPI>
__device__ __forceinline__ void epi_store(int row, int col, float v) {
    if (EPI == 0) {
        if (col < 64) g_XC0[row*LDA0 + 1 + col] = v * g_h0[row*64 + col];
        else          g_u[row*64 + col - 64] = v;
    } else if (EPI == 2) {
        if (col < 64) g_XC1[row*LDA1 + 64 + col] = v * g_h1[row*64 + col];
        else          g_u[row*64 + col - 64] = v;
    } else if (EPI == 1) {
        int i6 = row*64 + col;
        float u = g_u[i6];
        float hn = u * g_h0[i6] + (1.f - u) * v;
        g_h0[i6] = hn;
        g_XG0[row*LDA0 + 1 + col] = hn;
        g_XG1[row*LDA1 + col] = hn;
        g_XC1[row*LDA1 + col] = hn;
    } else {
        int i6 = row*64 + col;
        float u = g_u[i6];
        float hn = u * g_h1[i6] + (1.f - u) * v;
        g_h1[i6] = hn;
        g_XG1[row*LDA1 + 64 + col] = hn;
    }
}

template<int EPI>
__global__ __launch_bounds__(256) void gemm_tc(const float* __restrict__ bias) {
    constexpr int OUT = (EPI == 0 || EPI == 2) ? 128 : 64;
    constexpr int LDA = (EPI < 2) ? LDA0 : LDA1;
    constexpr int NKT = (EPI < 2) ? K0NKT : K1NKT;
    const float* __restrict__ X  = (EPI==0) ? g_XG0 : (EPI==1) ? g_XC0
                                  : (EPI==2) ? g_XG1 : g_XC1;
    const float* __restrict__ Wp = (EPI==0) ? g_Wg0 : (EPI==1) ? g_Wc0
                                  : (EPI==2) ? g_Wg1 : g_Wc1;
    __shared__ __align__(16) float As[2][128][20];
    __shared__ __align__(16) float Bs[2][16][72];
    const int tid = threadIdx.x, lane = tid & 31, warp = tid >> 5;
    const int m0 = blockIdx.x * 128, n0 = blockIdx.y * 64;
    const int wm = (warp >> 1) * 32, wn = (warp & 1) * 32;
    const int g = lane >> 2, t4 = lane & 3;

    float acc[2][4][4];
#pragma unroll
    for (int i = 0; i < 2; i++)
#pragma unroll
        for (int j = 0; j < 4; j++)
#pragma unroll
            for (int q = 0; q < 4; q++) acc[i][j][q] = 0.f;

    int arow[2], akc[2];
#pragma unroll
    for (int it = 0; it < 2; it++) { int fid = tid + it*256; arow[it] = fid >> 2; akc[it] = (fid & 3) * 4; }
    const int brow = tid >> 4, bnc = (tid & 15) * 4;

    float4 ra[2], rb;
#pragma unroll
    for (int it = 0; it < 2; it++)
        ra[it] = *(const float4*)(X + (size_t)(m0 + arow[it]) * LDA + akc[it]);
    rb = *(const float4*)(Wp + (size_t)brow * OUT + n0 + bnc);
#pragma unroll
    for (int it = 0; it < 2; it++) *(float4*)&As[0][arow[it]][akc[it]] = tf4(ra[it]);
    *(float4*)&Bs[0][brow][bnc] = tf4(rb);
    __syncthreads();

    for (int kt = 0; kt < NKT; kt++) {
        int cur = kt & 1;
        if (kt + 1 < NKT) {
            const float* Xp = X + (kt + 1) * 16;
#pragma unroll
            for (int it = 0; it < 2; it++)
                ra[it] = *(const float4*)(Xp + (size_t)(m0 + arow[it]) * LDA + akc[it]);
            rb = *(const float4*)(Wp + (size_t)((kt + 1) * 16 + brow) * OUT + n0 + bnc);
        }
#pragma unroll
        for (int kk = 0; kk < 16; kk += 8) {
            unsigned af[2][4], bf[4][2];
#pragma unroll
            for (int i = 0; i < 2; i++) {
                af[i][0] = __float_as_uint(As[cur][wm + i*16 + g    ][kk + t4]);
                af[i][1] = __float_as_uint(As[cur][wm + i*16 + g + 8][kk + t4]);
                af[i][2] = __float_as_uint(As[cur][wm + i*16 + g    ][kk + t4 + 4]);
                af[i][3] = __float_as_uint(As[cur][wm + i*16 + g + 8][kk + t4 + 4]);
            }
#pragma unroll
            for (int j = 0; j < 4; j++) {
                bf[j][0] = __float_as_uint(Bs[cur][kk + t4    ][wn + j*8 + g]);
                bf[j][1] = __float_as_uint(Bs[cur][kk + t4 + 4][wn + j*8 + g]);
            }
#pragma unroll
            for (int i = 0; i < 2; i++)
#pragma unroll
                for (int j = 0; j < 4; j++)
                    asm volatile(
                        "mma.sync.aligned.m16n8k8.row.col.f32.tf32.tf32.f32 "
                        "{%0,%1,%2,%3}, {%4,%5,%6,%7}, {%8,%9}, {%0,%1,%2,%3};"
                        : "+f"(acc[i][j][0]), "+f"(acc[i][j][1]),
                          "+f"(acc[i][j][2]), "+f"(acc[i][j][3])
                        : "r"(af[i][0]), "r"(af[i][1]), "r"(af[i][2]), "r"(af[i][3]),
                          "r"(bf[j][0]), "r"(bf[j][1]));
        }
        if (kt + 1 < NKT) {
            int nxt = cur ^ 1;
#pragma unroll
            for (int it = 0; it < 2; it++) *(float4*)&As[nxt][arow[it]][akc[it]] = tf4(ra[it]);
            *(float4*)&Bs[nxt][brow][bnc] = tf4(rb);
        }
        __syncthreads();
    }

#pragma unroll
    for (int j = 0; j < 4; j++) {
        int cb = n0 + wn + j*8 + 2*t4;
        float b0 = bias[cb], b1 = bias[cb + 1];
#pragma unroll
        for (int i = 0; i < 2; i++) {
            int r0 = m0 + wm + i*16 + g;
            float v0 = acc[i][j][0] + b0, v1 = acc[i][j][1] + b1;
            float v2 = acc[i][j][2] + b0, v3 = acc[i][j][3] + b1;
            if ((EPI & 1) == 0) {
                v0 = 1.f/(1.f+expf(-v0)); v1 = 1.f/(1.f+expf(-v1));
                v2 = 1.f/(1.f+expf(-v2)); v3 = 1.f/(1.f+expf(-v3));
            } else {
                v0 = tanhf(v0); v1 = tanhf(v1); v2 = tanhf(v2); v3 = tanhf(v3);
            }
            epi_store<EPI>(r0,     cb,     v0);
            epi_store<EPI>(r0,     cb + 1, v1);
            epi_store<EPI>(r0 + 8, cb,     v2);
            epi_store<EPI>(r0 + 8, cb + 1, v3);
        }
    }
}

__global__ void proj_k(const float* __restrict__ pw, const float* __restrict__ pb,
                       float* __restrict__ out, int t) {
    int idx = blockIdx.x * 256 + threadIdx.x;
    if (idx >= NB) return;
    int n = idx >> 7, b = idx & 127;
    float s = pb[0];
    const float* hh = &g_h1[idx * UNITS];
#pragma unroll
    for (int k = 0; k < UNITS; k++) s += hh[k] * pw[k];
    out[(b * T_OUTS + t) * N_NODES + n] = s;
    g_XG0[idx*LDA0] = s;
    g_XC0[idx*LDA0] = s;
}

// ---------------- host orchestration ----------------
#define SMEMF0 (2*512*36*4)   // 147456 B
#define SMEMF1 (2*512*32*4)   // 131072 B

static void launch_gconv(int lay, int sel) {
    if (lay == 0) spmm_fused_k<0><<<dim3(256,1,2), 512, SMEMF0>>>(sel);
    else          spmm_fused_k<1><<<dim3(512,1,2), 512, SMEMF1>>>(sel);
}
static void launch_step(const float* bg0, const float* bc0,
                        const float* bg1, const float* bc1) {
    launch_gconv(0, 0);
    gemm_tc<0><<<dim3(512, 2), 256>>>(bg0);
    launch_gconv(0, 1);
    gemm_tc<1><<<dim3(512, 1), 256>>>(bc0);
    launch_gconv(1, 0);
    gemm_tc<2><<<dim3(512, 2), 256>>>(bg1);
    launch_gconv(1, 1);
    gemm_tc<3><<<dim3(512, 1), 256>>>(bc1);
}

extern "C" void kernel_launch(void* const* d_in, const int* in_sizes, int n_in,
                              void* d_out, int out_size) {
    const float* hist = (const float*)d_in[0];
    const int*   ei   = (const int*)d_in[1];
    const float* ea   = (const float*)d_in[2];
    const float* W[16];
    for (int i = 0; i < 16; i++) W[i] = (const float*)d_in[3 + i];
    const float* pw = (const float*)d_in[19];
    const float* pb = (const float*)d_in[20];
    float* out = (float*)d_out;

    cudaFuncSetAttribute(spmm_fused_k<0>, cudaFuncAttributeMaxDynamicSharedMemorySize, SMEMF0);
    cudaFuncSetAttribute(spmm_fused_k<1>, cudaFuncAttributeMaxDynamicSharedMemorySize, SMEMF1);

    // --- supports + state setup ---
    zero_setup_k<<<(N_NODES*N_NODES)/256, 256>>>();
    zero_state_k<<<(NB*128)/256, 256>>>();
    scatter_k<<<E_EDGES/256, 256>>>(ei, ea);
    rowinv_k<<<N_NODES, 256>>>();
    colinv_k<<<2, 256>>>();
    count_k<<<(N_NODES*N_NODES)/256, 256>>>();
    scan_k<<<1, 32>>>();
    fill_k<<<(N_NODES*N_NODES)/256, 256>>>();

    // --- permute encoder weights ---
    permW_k<<<(M_DIFF*C0*128 + 255)/256, 256>>>(W[0], 0, C0, SL0, 128);
    permW_k<<<(M_DIFF*C0*64  + 255)/256, 256>>>(W[2], 1, C0, SL0, 64);
    permW_k<<<(M_DIFF*C1*128 + 255)/256, 256>>>(W[4], 2, C1, SL1, 128);
    permW_k<<<(M_DIFF*C1*64  + 255)/256, 256>>>(W[6], 3, C1, SL1, 64);

    // --- encoder ---
    for (int t = 0; t < T_INS; t++) {
        in_k<<<(NB + 255)/256, 256>>>(hist + (size_t)t * NB);
        launch_step(W[1], W[3], W[5], W[7]);
    }

    // --- permute decoder weights ---
    permW_k<<<(M_DIFF*C0*128 + 255)/256, 256>>>(W[8],  0, C0, SL0, 128);
    permW_k<<<(M_DIFF*C0*64  + 255)/256, 256>>>(W[10], 1, C0, SL0, 64);
    permW_k<<<(M_DIFF*C1*128 + 255)/256, 256>>>(W[12], 2, C1, SL1, 128);
    permW_k<<<(M_DIFF*C1*64  + 255)/256, 256>>>(W[14], 3, C1, SL1, 64);

    // --- decoder ---
    zgo_k<<<(NB + 255)/256, 256>>>();
    for (int t = 0; t < T_OUTS; t++) {
        launch_step(W[9], W[11], W[13], W[15]);
        proj_k<<<(NB + 255)/256, 256>>>(pw, pb, out, t);
    }
}

// round 12
// speedup vs baseline: 1.6490x; 1.6490x over previous
#include <cuda_runtime.h>
#include <math.h>

#define N_NODES 512
#define BATCH   128
#define UNITS   64
#define M_DIFF  5
#define E_EDGES 8192
#define T_INS   12
#define T_OUTS  12
#define NB      (N_NODES*BATCH)   // 65536
#define C0      65
#define C1      128
#define SL0     72                // layer0 per-m slice stride (pad 65->72)
#define SL1     128
#define LDA0    368               // 5*72 = 360, padded to 368 (mult of 16)
#define LDA1    640               // 5*128
#define K0NKT   23                // 368/16
#define K1NKT   40                // 640/16

// ---------------- scratch (static __device__, zero-init, no allocation) ----
__device__ float g_A[N_NODES*N_NODES];
__device__ float g_invrow[N_NODES];
__device__ float g_invcol[N_NODES];
__device__ int   g_cnt1[N_NODES], g_cnt2[N_NODES];
__device__ int   g_ptr1[N_NODES+1], g_ptr2[N_NODES+1];
__device__ int   g_cur1[N_NODES], g_cur2[N_NODES];
__device__ int   g_col1[E_EDGES], g_col2[E_EDGES];
__device__ float g_val1[E_EDGES], g_val2[E_EDGES];
__device__ float g_XG0[NB*LDA0];   // gate0 stack  [nb, m*72+c], pad cols stay zero
__device__ float g_XC0[NB*LDA0];   // cand0 stack
__device__ float g_XG1[NB*LDA1];   // gate1 stack  [nb, m*128+c]
__device__ float g_XC1[NB*LDA1];   // cand1 stack
__device__ float g_u  [NB*UNITS];  // update gate
__device__ float g_h0 [NB*UNITS];
__device__ float g_h1 [NB*UNITS];
__device__ float g_Wg0[LDA0*2*UNITS];  // permuted weights, k = m*SL+c, pads zero
__device__ float g_Wc0[LDA0*UNITS];
__device__ float g_Wg1[LDA1*2*UNITS];
__device__ float g_Wc1[LDA1*UNITS];

// ---------------- setup kernels ----------------
__global__ void zero_setup_k() {
    int idx = blockIdx.x * 256 + threadIdx.x;
    if (idx < N_NODES*N_NODES) g_A[idx] = 0.f;
    if (idx < N_NODES) { g_cnt1[idx]=0; g_cnt2[idx]=0; g_cur1[idx]=0; g_cur2[idx]=0; }
}
__global__ void zero_state_k() {
    int idx = blockIdx.x * 256 + threadIdx.x;
    if (idx >= NB*128) return;
    int nb = idx >> 7, cc = idx & 127;
    g_XG1[nb*LDA1 + cc] = 0.f;
    if (cc < 64) {
        g_h0[nb*64 + cc] = 0.f;
        g_h1[nb*64 + cc] = 0.f;
        g_XG0[nb*LDA0 + 1 + cc] = 0.f;
    }
}
__global__ void zgo_k() {
    int idx = blockIdx.x * 256 + threadIdx.x;
    if (idx < NB) { g_XG0[idx*LDA0] = 0.f; g_XC0[idx*LDA0] = 0.f; }
}
__global__ void scatter_k(const int* __restrict__ ei, const float* __restrict__ ea) {
    int e = blockIdx.x * 256 + threadIdx.x;
    if (e < E_EDGES) atomicAdd(&g_A[ei[e]*N_NODES + ei[E_EDGES+e]], ea[e]);
}
__global__ void rowinv_k() {
    __shared__ float sh[256];
    int r = blockIdx.x;
    float s = 0.f;
    for (int j = threadIdx.x; j < N_NODES; j += 256) s += g_A[r*N_NODES + j];
    sh[threadIdx.x] = s; __syncthreads();
    for (int o = 128; o > 0; o >>= 1) {
        if (threadIdx.x < o) sh[threadIdx.x] += sh[threadIdx.x + o];
        __syncthreads();
    }
    if (threadIdx.x == 0) { float d = sh[0]; g_invrow[r] = d > 0.f ? 1.f/d : 0.f; }
}
__global__ void colinv_k() {
    int c = blockIdx.x * 256 + threadIdx.x;
    if (c < N_NODES) {
        float s = 0.f;
        for (int i = 0; i < N_NODES; i++) s += g_A[i*N_NODES + c];
        g_invcol[c] = s > 0.f ? 1.f/s : 0.f;
    }
}
__global__ void count_k() {
    int idx = blockIdx.x * 256 + threadIdx.x;
    if (idx >= N_NODES*N_NODES) return;
    if (g_A[idx] != 0.f) {
        int i = idx / N_NODES, j = idx - i*N_NODES;
        atomicAdd(&g_cnt2[i], 1);
        atomicAdd(&g_cnt1[j], 1);
    }
}
__global__ void scan_k() {
    if (threadIdx.x == 0) {
        int s = 0;
        for (int i = 0; i < N_NODES; i++) { g_ptr1[i] = s; s += g_cnt1[i]; }
        g_ptr1[N_NODES] = s;
    }
    if (threadIdx.x == 1) {
        int s = 0;
        for (int i = 0; i < N_NODES; i++) { g_ptr2[i] = s; s += g_cnt2[i]; }
        g_ptr2[N_NODES] = s;
    }
}
__global__ void fill_k() {
    int idx = blockIdx.x * 256 + threadIdx.x;
    if (idx >= N_NODES*N_NODES) return;
    float a = g_A[idx];
    if (a != 0.f) {
        int i = idx / N_NODES, j = idx - i*N_NODES;
        int p2 = atomicAdd(&g_cur2[i], 1);
        int o2 = g_ptr2[i] + p2;
        g_col2[o2] = j; g_val2[o2] = a * g_invcol[j];
        int p1 = atomicAdd(&g_cur1[j], 1);
        int o1 = g_ptr1[j] + p1;
        g_col1[o1] = i; g_val1[o1] = a * g_invrow[i];
    }
}
// permute + Chebyshev-fold:  dest row (m*SL + c) gets
//   m=0: W0 - W2 - W4 ; m=1: W1 ; m=2: 2*W2 ; m=3: W3 ; m=4: 2*W4
__global__ void permW_k(const float* __restrict__ W, int dsel, int C, int SL, int OUT) {
    int idx = blockIdx.x * 256 + threadIdx.x;
    int tot = M_DIFF * C * OUT;
    if (idx >= tot) return;
    int o = idx % OUT, rc = idx / OUT;
    int m = rc / C, c = rc - m*C;
    float v;
    if (m == 0)
        v = W[(c*M_DIFF+0)*OUT+o] - W[(c*M_DIFF+2)*OUT+o] - W[(c*M_DIFF+4)*OUT+o];
    else if (m == 2) v = 2.f * W[(c*M_DIFF+2)*OUT+o];
    else if (m == 4) v = 2.f * W[(c*M_DIFF+4)*OUT+o];
    else             v = W[(c*M_DIFF+m)*OUT+o];
    float* dst = (dsel==0) ? g_Wg0 : (dsel==1) ? g_Wc0 : (dsel==2) ? g_Wg1 : g_Wc1;
    dst[(m*SL + c)*OUT + o] = v;
}

// ---------------- per-step kernels ----------------
__global__ void in_k(const float* __restrict__ hist_t) {
    int idx = blockIdx.x * 256 + threadIdx.x;
    if (idx >= NB) return;
    int b = idx >> 9, n = idx & 511;
    float v = hist_t[idx];
    int nb = n*BATCH + b;
    g_XG0[nb*LDA0] = v;
    g_XC0[nb*LDA0] = v;
}

// ---- fused two-phase SMEM-tile SpMM, occupancy-tuned, float4 LDS.
// Single [512 x TW] tile buffer. phase0: x1 = S@x0 (tile) -> global;
// reload x1 tile from global (L2-hot, __syncthreads gives intra-block
// visibility); phase1: x2 = S@x1 -> global. Chebyshev folded into weights.
template<int LAY>
__global__ void __launch_bounds__(512, LAY + 2) spmm_fused_k(int sel) {
    constexpr int TW  = LAY ? 32 : 36;
    constexpr int G   = TW / 4;            // float4 groups per row: 8 / 9
    constexpr int SL  = LAY ? SL1 : SL0;
    constexpr int LDA = LAY ? LDA1 : LDA0;
    constexpr int SH  = LAY ? 2 : 1;       // tiles per batch = 1<<SH
    constexpr int NSTR= LAY ? 64 : 56;     // stream groups
    constexpr int NPS = LAY ? 8 : 10;      // max nodes per stream
    extern __shared__ float sm[];          // 512*TW floats
    float4* smf4 = (float4*)sm;
    float* XS = LAY ? (sel ? g_XC1 : g_XG1) : (sel ? g_XC0 : g_XG0);
    const int sup = blockIdx.z;
    const int b     = blockIdx.x >> SH;
    const int cbase = (blockIdx.x & ((1<<SH)-1)) * TW;
    const int*   rp = sup ? g_ptr2 : g_ptr1;
    const int*   ci = sup ? g_col2 : g_col1;
    const float* cv = sup ? g_val2 : g_val1;
    const int tid = threadIdx.x;

    const int c4     = LAY ? (tid & 7)  : (tid % 9);
    const int stream = LAY ? (tid >> 3) : (tid / 9);
    const bool active = LAY ? true : (tid < 504);

    // load x0 tile (slice 0)
    for (int idx = tid; idx < 512*G; idx += 512) {
        int n = idx / G, w = idx - n*G;
        smf4[n*G + w] = *(const float4*)&XS[(n*BATCH + b)*LDA + cbase + w*4];
    }
    __syncthreads();

    const int oo0 = (1 + 2*sup)*SL + cbase + c4*4;
    if (active) {
#pragma unroll
        for (int s = 0; s < NPS; s++) {
            int n = stream + s*NSTR;
            if (n < N_NODES) {
                int e0 = rp[n], e1 = rp[n+1];
                float4 a = {0.f,0.f,0.f,0.f}, bb = {0.f,0.f,0.f,0.f};
                int e = e0;
                for (; e + 2 <= e1; e += 2) {
                    float v0 = cv[e], v1 = cv[e+1];
                    float4 xa = smf4[ci[e]*G + c4];
                    float4 xb = smf4[ci[e+1]*G + c4];
                    a.x += v0*xa.x; a.y += v0*xa.y; a.z += v0*xa.z; a.w += v0*xa.w;
                    bb.x += v1*xb.x; bb.y += v1*xb.y; bb.z += v1*xb.z; bb.w += v1*xb.w;
                }
                if (e < e1) {
                    float v0 = cv[e];
                    float4 xa = smf4[ci[e]*G + c4];
                    a.x += v0*xa.x; a.y += v0*xa.y; a.z += v0*xa.z; a.w += v0*xa.w;
                }
                float4 r;
                r.x = a.x + bb.x; r.y = a.y + bb.y; r.z = a.z + bb.z; r.w = a.w + bb.w;
                *(float4*)&XS[(n*BATCH + b)*LDA + oo0] = r;
            }
        }
    }
    __syncthreads();   // x1 global writes visible block-wide

    // reload x1 tile (written by this block; L2-hot)
    {
        const int ib = (1 + 2*sup)*SL + cbase;
        for (int idx = tid; idx < 512*G; idx += 512) {
            int n = idx / G, w = idx - n*G;
            smf4[n*G + w] = *(const float4*)&XS[(n*BATCH + b)*LDA + ib + w*4];
        }
    }
    __syncthreads();

    const int oo1 = (2 + 2*sup)*SL + cbase + c4*4;
    if (active) {
#pragma unroll
        for (int s = 0; s < NPS; s++) {
            int n = stream + s*NSTR;
            if (n < N_NODES) {
                int e0 = rp[n], e1 = rp[n+1];
                float4 a = {0.f,0.f,0.f,0.f}, bb = {0.f,0.f,0.f,0.f};
                int e = e0;
                for (; e + 2 <= e1; e += 2) {
                    float v0 = cv[e], v1 = cv[e+1];
                    float4 xa = smf4[ci[e]*G + c4];
                    float4 xb = smf4[ci[e+1]*G + c4];
                    a.x += v0*xa.x; a.y += v0*xa.y; a.z += v0*xa.z; a.w += v0*xa.w;
                    bb.x += v1*xb.x; bb.y += v1*xb.y; bb.z += v1*xb.z; bb.w += v1*xb.w;
                }
                if (e < e1) {
                    float v0 = cv[e];
                    float4 xa = smf4[ci[e]*G + c4];
                    a.x += v0*xa.x; a.y += v0*xa.y; a.z += v0*xa.z; a.w += v0*xa.w;
                }
                float4 r;
                r.x = a.x + bb.x; r.y = a.y + bb.y; r.z = a.z + bb.z; r.w = a.w + bb.w;
                *(float4*)&XS[(n*BATCH + b)*LDA + oo1] = r;
            }
        }
    }
}

// ---------------- TF32 tensor-core GEMM with fused DCGRU epilogues ----------
__device__ __forceinline__ unsigned f2tf(float f) {
    unsigned u; asm("cvt.rna.tf32.f32 %0, %1;" : "=r"(u) : "f"(f)); return u;
}
__device__ __forceinline__ float4 tf4(float4 v) {
    float4 r;
    r.x = __uint_as_float(f2tf(v.x)); r.y = __uint_as_float(f2tf(v.y));
    r.z = __uint_as_float(f2tf(v.z)); r.w = __uint_as_float(f2tf(v.w));
    return r;
}
// EPI: 0=gate0 (A=XG0, sigmoid, writes r*h0->XC0, u->g_u)
//      1=cand0 (A=XC0, tanh, h0n -> g_h0, XG0, XG1[0:64), XC1[0:64))
//      2=gate1 (A=XG1, sigmoid, writes r*h1->XC1[64:), u->g_u)
//      3=cand1 (A=XC1, tanh, h1n -> g_h1, XG1[64:))
template<int EPI>
__device__ __forceinline__ void epi_store(int row, int col, float v) {
    if (EPI == 0) {
        if (col < 64) g_XC0[row*LDA0 + 1 + col] = v * g_h0[row*64 + col];
        else          g_u[row*64 + col - 64] = v;
    } else if (EPI == 2) {
        if (col < 64) g_XC1[row*LDA1 + 64 + col] = v * g_h1[row*64 + col];
        else          g_u[row*64 + col - 64] = v;
    } else if (EPI == 1) {
        int i6 = row*64 + col;
        float u = g_u[i6];
        float hn = u * g_h0[i6] + (1.f - u) * v;
        g_h0[i6] = hn;
        g_XG0[row*LDA0 + 1 + col] = hn;
        g_XG1[row*LDA1 + col] = hn;
        g_XC1[row*LDA1 + col] = hn;
    } else {
        int i6 = row*64 + col;
        float u = g_u[i6];
        float hn = u * g_h1[i6] + (1.f - u) * v;
        g_h1[i6] = hn;
        g_XG1[row*LDA1 + 64 + col] = hn;
    }
}

template<int EPI>
__global__ __launch_bounds__(256) void gemm_tc(const float* __restrict__ bias) {
    constexpr int OUT = (EPI == 0 || EPI == 2) ? 128 : 64;
    constexpr int LDA = (EPI < 2) ? LDA0 : LDA1;
    constexpr int NKT = (EPI < 2) ? K0NKT : K1NKT;
    const float* __restrict__ X  = (EPI==0) ? g_XG0 : (EPI==1) ? g_XC0
                                  : (EPI==2) ? g_XG1 : g_XC1;
    const float* __restrict__ Wp = (EPI==0) ? g_Wg0 : (EPI==1) ? g_Wc0
                                  : (EPI==2) ? g_Wg1 : g_Wc1;
    __shared__ __align__(16) float As[2][128][20];
    __shared__ __align__(16) float Bs[2][16][72];
    const int tid = threadIdx.x, lane = tid & 31, warp = tid >> 5;
    const int m0 = blockIdx.x * 128, n0 = blockIdx.y * 64;
    const int wm = (warp >> 1) * 32, wn = (warp & 1) * 32;
    const int g = lane >> 2, t4 = lane & 3;

    float acc[2][4][4];
#pragma unroll
    for (int i = 0; i < 2; i++)
#pragma unroll
        for (int j = 0; j < 4; j++)
#pragma unroll
            for (int q = 0; q < 4; q++) acc[i][j][q] = 0.f;

    int arow[2], akc[2];
#pragma unroll
    for (int it = 0; it < 2; it++) { int fid = tid + it*256; arow[it] = fid >> 2; akc[it] = (fid & 3) * 4; }
    const int brow = tid >> 4, bnc = (tid & 15) * 4;

    float4 ra[2], rb;
#pragma unroll
    for (int it = 0; it < 2; it++)
        ra[it] = *(const float4*)(X + (size_t)(m0 + arow[it]) * LDA + akc[it]);
    rb = *(const float4*)(Wp + (size_t)brow * OUT + n0 + bnc);
#pragma unroll
    for (int it = 0; it < 2; it++) *(float4*)&As[0][arow[it]][akc[it]] = tf4(ra[it]);
    *(float4*)&Bs[0][brow][bnc] = tf4(rb);
    __syncthreads();

    for (int kt = 0; kt < NKT; kt++) {
        int cur = kt & 1;
        if (kt + 1 < NKT) {
            const float* Xp = X + (kt + 1) * 16;
#pragma unroll
            for (int it = 0; it < 2; it++)
                ra[it] = *(const float4*)(Xp + (size_t)(m0 + arow[it]) * LDA + akc[it]);
            rb = *(const float4*)(Wp + (size_t)((kt + 1) * 16 + brow) * OUT + n0 + bnc);
        }
#pragma unroll
        for (int kk = 0; kk < 16; kk += 8) {
            unsigned af[2][4], bf[4][2];
#pragma unroll
            for (int i = 0; i < 2; i++) {
                af[i][0] = __float_as_uint(As[cur][wm + i*16 + g    ][kk + t4]);
                af[i][1] = __float_as_uint(As[cur][wm + i*16 + g + 8][kk + t4]);
                af[i][2] = __float_as_uint(As[cur][wm + i*16 + g    ][kk + t4 + 4]);
                af[i][3] = __float_as_uint(As[cur][wm + i*16 + g + 8][kk + t4 + 4]);
            }
#pragma unroll
            for (int j = 0; j < 4; j++) {
                bf[j][0] = __float_as_uint(Bs[cur][kk + t4    ][wn + j*8 + g]);
                bf[j][1] = __float_as_uint(Bs[cur][kk + t4 + 4][wn + j*8 + g]);
            }
#pragma unroll
            for (int i = 0; i < 2; i++)
#pragma unroll
                for (int j = 0; j < 4; j++)
                    asm volatile(
                        "mma.sync.aligned.m16n8k8.row.col.f32.tf32.tf32.f32 "
                        "{%0,%1,%2,%3}, {%4,%5,%6,%7}, {%8,%9}, {%0,%1,%2,%3};"
                        : "+f"(acc[i][j][0]), "+f"(acc[i][j][1]),
                          "+f"(acc[i][j][2]), "+f"(acc[i][j][3])
                        : "r"(af[i][0]), "r"(af[i][1]), "r"(af[i][2]), "r"(af[i][3]),
                          "r"(bf[j][0]), "r"(bf[j][1]));
        }
        if (kt + 1 < NKT) {
            int nxt = cur ^ 1;
#pragma unroll
            for (int it = 0; it < 2; it++) *(float4*)&As[nxt][arow[it]][akc[it]] = tf4(ra[it]);
            *(float4*)&Bs[nxt][brow][bnc] = tf4(rb);
        }
        __syncthreads();
    }

#pragma unroll
    for (int j = 0; j < 4; j++) {
        int cb = n0 + wn + j*8 + 2*t4;
        float b0 = bias[cb], b1 = bias[cb + 1];
#pragma unroll
        for (int i = 0; i < 2; i++) {
            int r0 = m0 + wm + i*16 + g;
            float v0 = acc[i][j][0] + b0, v1 = acc[i][j][1] + b1;
            float v2 = acc[i][j][2] + b0, v3 = acc[i][j][3] + b1;
            if ((EPI & 1) == 0) {
                v0 = 1.f/(1.f+expf(-v0)); v1 = 1.f/(1.f+expf(-v1));
                v2 = 1.f/(1.f+expf(-v2)); v3 = 1.f/(1.f+expf(-v3));
            } else {
                v0 = tanhf(v0); v1 = tanhf(v1); v2 = tanhf(v2); v3 = tanhf(v3);
            }
            epi_store<EPI>(r0,     cb,     v0);
            epi_store<EPI>(r0,     cb + 1, v1);
            epi_store<EPI>(r0 + 8, cb,     v2);
            epi_store<EPI>(r0 + 8, cb + 1, v3);
        }
    }
}

__global__ void proj_k(const float* __restrict__ pw, const float* __restrict__ pb,
                       float* __restrict__ out, int t) {
    int idx = blockIdx.x * 256 + threadIdx.x;
    if (idx >= NB) return;
    int n = idx >> 7, b = idx & 127;
    float s = pb[0];
    const float* hh = &g_h1[idx * UNITS];
#pragma unroll
    for (int k = 0; k < UNITS; k++) s += hh[k] * pw[k];
    out[(b * T_OUTS + t) * N_NODES + n] = s;
    g_XG0[idx*LDA0] = s;
    g_XC0[idx*LDA0] = s;
}

// ---------------- host orchestration ----------------
#define SMEMF0 (512*36*4)   // 73728 B  -> 2 CTAs/SM
#define SMEMF1 (512*32*4)   // 65536 B  -> 3 CTAs/SM

static void launch_gconv(int lay, int sel) {
    if (lay == 0) spmm_fused_k<0><<<dim3(256,1,2), 512, SMEMF0>>>(sel);
    else          spmm_fused_k<1><<<dim3(512,1,2), 512, SMEMF1>>>(sel);
}
static void launch_step(const float* bg0, const float* bc0,
                        const float* bg1, const float* bc1) {
    launch_gconv(0, 0);
    gemm_tc<0><<<dim3(512, 2), 256>>>(bg0);
    launch_gconv(0, 1);
    gemm_tc<1><<<dim3(512, 1), 256>>>(bc0);
    launch_gconv(1, 0);
    gemm_tc<2><<<dim3(512, 2), 256>>>(bg1);
    launch_gconv(1, 1);
    gemm_tc<3><<<dim3(512, 1), 256>>>(bc1);
}

extern "C" void kernel_launch(void* const* d_in, const int* in_sizes, int n_in,
                              void* d_out, int out_size) {
    const float* hist = (const float*)d_in[0];
    const int*   ei   = (const int*)d_in[1];
    const float* ea   = (const float*)d_in[2];
    const float* W[16];
    for (int i = 0; i < 16; i++) W[i] = (const float*)d_in[3 + i];
    const float* pw = (const float*)d_in[19];
    const float* pb = (const float*)d_in[20];
    float* out = (float*)d_out;

    cudaFuncSetAttribute(spmm_fused_k<0>, cudaFuncAttributeMaxDynamicSharedMemorySize, SMEMF0);
    cudaFuncSetAttribute(spmm_fused_k<1>, cudaFuncAttributeMaxDynamicSharedMemorySize, SMEMF1);

    // --- supports + state setup ---
    zero_setup_k<<<(N_NODES*N_NODES)/256, 256>>>();
    zero_state_k<<<(NB*128)/256, 256>>>();
    scatter_k<<<E_EDGES/256, 256>>>(ei, ea);
    rowinv_k<<<N_NODES, 256>>>();
    colinv_k<<<2, 256>>>();
    count_k<<<(N_NODES*N_NODES)/256, 256>>>();
    scan_k<<<1, 32>>>();
    fill_k<<<(N_NODES*N_NODES)/256, 256>>>();

    // --- permute encoder weights ---
    permW_k<<<(M_DIFF*C0*128 + 255)/256, 256>>>(W[0], 0, C0, SL0, 128);
    permW_k<<<(M_DIFF*C0*64  + 255)/256, 256>>>(W[2], 1, C0, SL0, 64);
    permW_k<<<(M_DIFF*C1*128 + 255)/256, 256>>>(W[4], 2, C1, SL1, 128);
    permW_k<<<(M_DIFF*C1*64  + 255)/256, 256>>>(W[6], 3, C1, SL1, 64);

    // --- encoder ---
    for (int t = 0; t < T_INS; t++) {
        in_k<<<(NB + 255)/256, 256>>>(hist + (size_t)t * NB);
        launch_step(W[1], W[3], W[5], W[7]);
    }

    // --- permute decoder weights ---
    permW_k<<<(M_DIFF*C0*128 + 255)/256, 256>>>(W[8],  0, C0, SL0, 128);
    permW_k<<<(M_DIFF*C0*64  + 255)/256, 256>>>(W[10], 1, C0, SL0, 64);
    permW_k<<<(M_DIFF*C1*128 + 255)/256, 256>>>(W[12], 2, C1, SL1, 128);
    permW_k<<<(M_DIFF*C1*64  + 255)/256, 256>>>(W[14], 3, C1, SL1, 64);

    // --- decoder ---
    zgo_k<<<(NB + 255)/256, 256>>>();
    for (int t = 0; t < T_OUTS; t++) {
        launch_step(W[9], W[11], W[13], W[15]);
        proj_k<<<(NB + 255)/256, 256>>>(pw, pb, out, t);
    }
}

// round 16
// speedup vs baseline: 1.7455x; 1.0586x over previous
#include <cuda_runtime.h>
#include <math.h>

#define N_NODES 512
#define BATCH   128
#define UNITS   64
#define M_DIFF  5
#define E_EDGES 8192
#define T_INS   12
#define T_OUTS  12
#define NB      (N_NODES*BATCH)   // 65536
#define C0      65
#define C1      128
#define SL0     72
#define SL1     128
#define LDA0    368
#define LDA1    640
#define K0NKT   23
#define K1NKT   40

// ---------------- scratch (static __device__, zero-init, no allocation) ----
__device__ float g_A[N_NODES*N_NODES];
__device__ float g_invrow[N_NODES];
__device__ float g_invcol[N_NODES];
__device__ int   g_cnt1[N_NODES], g_cnt2[N_NODES];
__device__ int   g_ptr1[N_NODES+1], g_ptr2[N_NODES+1];
__device__ int   g_cur1[N_NODES], g_cur2[N_NODES];
__device__ int   g_col1[E_EDGES], g_col2[E_EDGES];
__device__ float g_val1[E_EDGES], g_val2[E_EDGES];
__device__ float g_XG0[NB*LDA0];
__device__ float g_XC0[NB*LDA0];
__device__ float g_XG1[NB*LDA1];
__device__ float g_XC1[NB*LDA1];
__device__ float g_u  [NB*UNITS];
__device__ float g_h0 [NB*UNITS];
__device__ float g_h1 [NB*UNITS];
__device__ float g_Wg0[LDA0*2*UNITS];
__device__ float g_Wc0[LDA0*UNITS];
__device__ float g_Wg1[LDA1*2*UNITS];
__device__ float g_Wc1[LDA1*UNITS];

// ---------------- setup kernels ----------------
__global__ void zero_setup_k() {
    int idx = blockIdx.x * 256 + threadIdx.x;
    if (idx < N_NODES*N_NODES) g_A[idx] = 0.f;
    if (idx < N_NODES) { g_cnt1[idx]=0; g_cnt2[idx]=0; g_cur1[idx]=0; g_cur2[idx]=0; }
}
__global__ void zero_state_k() {
    int idx = blockIdx.x * 256 + threadIdx.x;
    if (idx >= NB*128) return;
    int nb = idx >> 7, cc = idx & 127;
    g_XG1[nb*LDA1 + cc] = 0.f;
    if (cc < 64) {
        g_h0[nb*64 + cc] = 0.f;
        g_h1[nb*64 + cc] = 0.f;
        g_XG0[nb*LDA0 + 1 + cc] = 0.f;
    }
}
__global__ void zgo_k() {
    int idx = blockIdx.x * 256 + threadIdx.x;
    if (idx < NB) { g_XG0[idx*LDA0] = 0.f; g_XC0[idx*LDA0] = 0.f; }
}
__global__ void scatter_k(const int* __restrict__ ei, const float* __restrict__ ea) {
    int e = blockIdx.x * 256 + threadIdx.x;
    if (e < E_EDGES) atomicAdd(&g_A[ei[e]*N_NODES + ei[E_EDGES+e]], ea[e]);
}
__global__ void rowinv_k() {
    __shared__ float sh[256];
    int r = blockIdx.x;
    float s = 0.f;
    for (int j = threadIdx.x; j < N_NODES; j += 256) s += g_A[r*N_NODES + j];
    sh[threadIdx.x] = s; __syncthreads();
    for (int o = 128; o > 0; o >>= 1) {
        if (threadIdx.x < o) sh[threadIdx.x] += sh[threadIdx.x + o];
        __syncthreads();
    }
    if (threadIdx.x == 0) { float d = sh[0]; g_invrow[r] = d > 0.f ? 1.f/d : 0.f; }
}
__global__ void colinv_k() {
    int c = blockIdx.x * 256 + threadIdx.x;
    if (c < N_NODES) {
        float s = 0.f;
        for (int i = 0; i < N_NODES; i++) s += g_A[i*N_NODES + c];
        g_invcol[c] = s > 0.f ? 1.f/s : 0.f;
    }
}
__global__ void count_k() {
    int idx = blockIdx.x * 256 + threadIdx.x;
    if (idx >= N_NODES*N_NODES) return;
    if (g_A[idx] != 0.f) {
        int i = idx / N_NODES, j = idx - i*N_NODES;
        atomicAdd(&g_cnt2[i], 1);
        atomicAdd(&g_cnt1[j], 1);
    }
}
__global__ void scan_k() {
    if (threadIdx.x == 0) {
        int s = 0;
        for (int i = 0; i < N_NODES; i++) { g_ptr1[i] = s; s += g_cnt1[i]; }
        g_ptr1[N_NODES] = s;
    }
    if (threadIdx.x == 1) {
        int s = 0;
        for (int i = 0; i < N_NODES; i++) { g_ptr2[i] = s; s += g_cnt2[i]; }
        g_ptr2[N_NODES] = s;
    }
}
__global__ void fill_k() {
    int idx = blockIdx.x * 256 + threadIdx.x;
    if (idx >= N_NODES*N_NODES) return;
    float a = g_A[idx];
    if (a != 0.f) {
        int i = idx / N_NODES, j = idx - i*N_NODES;
        int p2 = atomicAdd(&g_cur2[i], 1);
        int o2 = g_ptr2[i] + p2;
        g_col2[o2] = j; g_val2[o2] = a * g_invcol[j];
        int p1 = atomicAdd(&g_cur1[j], 1);
        int o1 = g_ptr1[j] + p1;
        g_col1[o1] = i; g_val1[o1] = a * g_invrow[i];
    }
}
// permute + Chebyshev-fold
__global__ void permW_k(const float* __restrict__ W, int dsel, int C, int SL, int OUT) {
    int idx = blockIdx.x * 256 + threadIdx.x;
    int tot = M_DIFF * C * OUT;
    if (idx >= tot) return;
    int o = idx % OUT, rc = idx / OUT;
    int m = rc / C, c = rc - m*C;
    float v;
    if (m == 0)
        v = W[(c*M_DIFF+0)*OUT+o] - W[(c*M_DIFF+2)*OUT+o] - W[(c*M_DIFF+4)*OUT+o];
    else if (m == 2) v = 2.f * W[(c*M_DIFF+2)*OUT+o];
    else if (m == 4) v = 2.f * W[(c*M_DIFF+4)*OUT+o];
    else             v = W[(c*M_DIFF+m)*OUT+o];
    float* dst = (dsel==0) ? g_Wg0 : (dsel==1) ? g_Wc0 : (dsel==2) ? g_Wg1 : g_Wc1;
    dst[(m*SL + c)*OUT + o] = v;
}

// ---------------- per-step kernels ----------------
__global__ void in_k(const float* __restrict__ hist_t) {
    int idx = blockIdx.x * 256 + threadIdx.x;
    if (idx >= NB) return;
    int b = idx >> 9, n = idx & 511;
    float v = hist_t[idx];
    int nb = n*BATCH + b;
    g_XG0[nb*LDA0] = v;
    g_XC0[nb*LDA0] = v;
}

// ---- fused two-phase SMEM-tile SpMM (unchanged from R12 pass) ----
template<int LAY>
__global__ void __launch_bounds__(512, LAY + 2) spmm_fused_k(int sel) {
    constexpr int TW  = LAY ? 32 : 36;
    constexpr int G   = TW / 4;
    constexpr int SL  = LAY ? SL1 : SL0;
    constexpr int LDA = LAY ? LDA1 : LDA0;
    constexpr int SH  = LAY ? 2 : 1;
    constexpr int NSTR= LAY ? 64 : 56;
    constexpr int NPS = LAY ? 8 : 10;
    extern __shared__ float sm[];
    float4* smf4 = (float4*)sm;
    float* XS = LAY ? (sel ? g_XC1 : g_XG1) : (sel ? g_XC0 : g_XG0);
    const int sup = blockIdx.z;
    const int b     = blockIdx.x >> SH;
    const int cbase = (blockIdx.x & ((1<<SH)-1)) * TW;
    const int*   rp = sup ? g_ptr2 : g_ptr1;
    const int*   ci = sup ? g_col2 : g_col1;
    const float* cv = sup ? g_val2 : g_val1;
    const int tid = threadIdx.x;

    const int c4     = LAY ? (tid & 7)  : (tid % 9);
    const int stream = LAY ? (tid >> 3) : (tid / 9);
    const bool active = LAY ? true : (tid < 504);

    for (int idx = tid; idx < 512*G; idx += 512) {
        int n = idx / G, w = idx - n*G;
        smf4[n*G + w] = *(const float4*)&XS[(n*BATCH + b)*LDA + cbase + w*4];
    }
    __syncthreads();

    const int oo0 = (1 + 2*sup)*SL + cbase + c4*4;
    if (active) {
#pragma unroll
        for (int s = 0; s < NPS; s++) {
            int n = stream + s*NSTR;
            if (n < N_NODES) {
                int e0 = rp[n], e1 = rp[n+1];
                float4 a = {0.f,0.f,0.f,0.f}, bb = {0.f,0.f,0.f,0.f};
                int e = e0;
                for (; e + 2 <= e1; e += 2) {
                    float v0 = cv[e], v1 = cv[e+1];
                    float4 xa = smf4[ci[e]*G + c4];
                    float4 xb = smf4[ci[e+1]*G + c4];
                    a.x += v0*xa.x; a.y += v0*xa.y; a.z += v0*xa.z; a.w += v0*xa.w;
                    bb.x += v1*xb.x; bb.y += v1*xb.y; bb.z += v1*xb.z; bb.w += v1*xb.w;
                }
                if (e < e1) {
                    float v0 = cv[e];
                    float4 xa = smf4[ci[e]*G + c4];
                    a.x += v0*xa.x; a.y += v0*xa.y; a.z += v0*xa.z; a.w += v0*xa.w;
                }
                float4 r;
                r.x = a.x + bb.x; r.y = a.y + bb.y; r.z = a.z + bb.z; r.w = a.w + bb.w;
                *(float4*)&XS[(n*BATCH + b)*LDA + oo0] = r;
            }
        }
    }
    __syncthreads();

    {
        const int ib = (1 + 2*sup)*SL + cbase;
        for (int idx = tid; idx < 512*G; idx += 512) {
            int n = idx / G, w = idx - n*G;
            smf4[n*G + w] = *(const float4*)&XS[(n*BATCH + b)*LDA + ib + w*4];
        }
    }
    __syncthreads();

    const int oo1 = (2 + 2*sup)*SL + cbase + c4*4;
    if (active) {
#pragma unroll
        for (int s = 0; s < NPS; s++) {
            int n = stream + s*NSTR;
            if (n < N_NODES) {
                int e0 = rp[n], e1 = rp[n+1];
                float4 a = {0.f,0.f,0.f,0.f}, bb = {0.f,0.f,0.f,0.f};
                int e = e0;
                for (; e + 2 <= e1; e += 2) {
                    float v0 = cv[e], v1 = cv[e+1];
                    float4 xa = smf4[ci[e]*G + c4];
                    float4 xb = smf4[ci[e+1]*G + c4];
                    a.x += v0*xa.x; a.y += v0*xa.y; a.z += v0*xa.z; a.w += v0*xa.w;
                    bb.x += v1*xb.x; bb.y += v1*xb.y; bb.z += v1*xb.z; bb.w += v1*xb.w;
                }
                if (e < e1) {
                    float v0 = cv[e];
                    float4 xa = smf4[ci[e]*G + c4];
                    a.x += v0*xa.x; a.y += v0*xa.y; a.z += v0*xa.z; a.w += v0*xa.w;
                }
                float4 r;
                r.x = a.x + bb.x; r.y = a.y + bb.y; r.z = a.z + bb.z; r.w = a.w + bb.w;
                *(float4*)&XS[(n*BATCH + b)*LDA + oo1] = r;
            }
        }
    }
}

// ---------------- TF32 tensor-core GEMM with fused DCGRU epilogues ----------
__device__ __forceinline__ unsigned f2tf(float f) {
    unsigned u; asm("cvt.rna.tf32.f32 %0, %1;" : "=r"(u) : "f"(f)); return u;
}
__device__ __forceinline__ float4 tf4(float4 v) {
    float4 r;
    r.x = __uint_as_float(f2tf(v.x)); r.y = __uint_as_float(f2tf(v.y));
    r.z = __uint_as_float(f2tf(v.z)); r.w = __uint_as_float(f2tf(v.w));
    return r;
}
template<int EPI>
__device__ __forceinline__ void epi_store(int row, int col, float v) {
    if (EPI == 0) {
        if (col < 64) g_XC0[row*LDA0 + 1 + col] = v * g_h0[row*64 + col];
        else          g_u[row*64 + col - 64] = v;
    } else if (EPI == 2) {
        if (col < 64) g_XC1[row*LDA1 + 64 + col] = v * g_h1[row*64 + col];
        else          g_u[row*64 + col - 64] = v;
    } else if (EPI == 1) {
        int i6 = row*64 + col;
        float u = g_u[i6];
        float hn = u * g_h0[i6] + (1.f - u) * v;
        g_h0[i6] = hn;
        g_XG0[row*LDA0 + 1 + col] = hn;
        g_XG1[row*LDA1 + col] = hn;
        g_XC1[row*LDA1 + col] = hn;
    } else {
        int i6 = row*64 + col;
        float u = g_u[i6];
        float hn = u * g_h1[i6] + (1.f - u) * v;
        g_h1[i6] = hn;
        g_XG1[row*LDA1 + 64 + col] = hn;
    }
}

// BM=128, BN=OUT (128 gates / 64 cand), BK=16, 256 thr = 8 warps (4M x 2N).
// Warp tile 32 x (BN/2). Grid: (512, 1).
template<int EPI>
__global__ __launch_bounds__(256) void gemm_tc(const float* __restrict__ bias) {
    constexpr int OUT = (EPI == 0 || EPI == 2) ? 128 : 64;
    constexpr int BN  = OUT;
    constexpr int JN  = BN / 16;          // 8 (gates) or 4 (cand): j-frags per warp
    constexpr int R4  = BN / 4;           // float4 per B row
    constexpr int NBLD= BN / 64;          // B float4 loads per thread (2 or 1)
    constexpr int BSTR= BN + 8;           // Bs row stride (conflict-free: stride%32=8)
    constexpr int LDA = (EPI < 2) ? LDA0 : LDA1;
    constexpr int NKT = (EPI < 2) ? K0NKT : K1NKT;
    const float* __restrict__ X  = (EPI==0) ? g_XG0 : (EPI==1) ? g_XC0
                                  : (EPI==2) ? g_XG1 : g_XC1;
    const float* __restrict__ Wp = (EPI==0) ? g_Wg0 : (EPI==1) ? g_Wc0
                                  : (EPI==2) ? g_Wg1 : g_Wc1;
    __shared__ __align__(16) float As[2][128][20];
    __shared__ __align__(16) float Bs[2][16][BSTR];
    const int tid = threadIdx.x, lane = tid & 31, warp = tid >> 5;
    const int m0 = blockIdx.x * 128;
    const int wm = (warp >> 1) * 32, wn = (warp & 1) * (BN/2);
    const int g = lane >> 2, t4 = lane & 3;

    float acc[2][JN][4];
#pragma unroll
    for (int i = 0; i < 2; i++)
#pragma unroll
        for (int j = 0; j < JN; j++)
#pragma unroll
            for (int q = 0; q < 4; q++) acc[i][j][q] = 0.f;

    int arow[2], akc[2];
#pragma unroll
    for (int it = 0; it < 2; it++) { int fid = tid + it*256; arow[it] = fid >> 2; akc[it] = (fid & 3) * 4; }
    int brow[NBLD], bnc[NBLD];
#pragma unroll
    for (int it = 0; it < NBLD; it++) {
        int fid = tid + it*256;
        brow[it] = fid / R4; bnc[it] = (fid % R4) * 4;
    }

    float4 ra[2], rb[NBLD];
#pragma unroll
    for (int it = 0; it < 2; it++)
        ra[it] = *(const float4*)(X + (size_t)(m0 + arow[it]) * LDA + akc[it]);
#pragma unroll
    for (int it = 0; it < NBLD; it++)
        rb[it] = *(const float4*)(Wp + (size_t)brow[it] * OUT + bnc[it]);
#pragma unroll
    for (int it = 0; it < 2; it++) *(float4*)&As[0][arow[it]][akc[it]] = tf4(ra[it]);
#pragma unroll
    for (int it = 0; it < NBLD; it++) *(float4*)&Bs[0][brow[it]][bnc[it]] = tf4(rb[it]);
    __syncthreads();

    for (int kt = 0; kt < NKT; kt++) {
        int cur = kt & 1;
        if (kt + 1 < NKT) {
            const float* Xp = X + (kt + 1) * 16;
#pragma unroll
            for (int it = 0; it < 2; it++)
                ra[it] = *(const float4*)(Xp + (size_t)(m0 + arow[it]) * LDA + akc[it]);
#pragma unroll
            for (int it = 0; it < NBLD; it++)
                rb[it] = *(const float4*)(Wp + (size_t)((kt + 1) * 16 + brow[it]) * OUT + bnc[it]);
        }
#pragma unroll
        for (int kk = 0; kk < 16; kk += 8) {
            unsigned af[2][4], bf[JN][2];
#pragma unroll
            for (int i = 0; i < 2; i++) {
                af[i][0] = __float_as_uint(As[cur][wm + i*16 + g    ][kk + t4]);
                af[i][1] = __float_as_uint(As[cur][wm + i*16 + g + 8][kk + t4]);
                af[i][2] = __float_as_uint(As[cur][wm + i*16 + g    ][kk + t4 + 4]);
                af[i][3] = __float_as_uint(As[cur][wm + i*16 + g + 8][kk + t4 + 4]);
            }
#pragma unroll
            for (int j = 0; j < JN; j++) {
                bf[j][0] = __float_as_uint(Bs[cur][kk + t4    ][wn + j*8 + g]);
                bf[j][1] = __float_as_uint(Bs[cur][kk + t4 + 4][wn + j*8 + g]);
            }
#pragma unroll
            for (int i = 0; i < 2; i++)
#pragma unroll
                for (int j = 0; j < JN; j++)
                    asm volatile(
                        "mma.sync.aligned.m16n8k8.row.col.f32.tf32.tf32.f32 "
                        "{%0,%1,%2,%3}, {%4,%5,%6,%7}, {%8,%9}, {%0,%1,%2,%3};"
                        : "+f"(acc[i][j][0]), "+f"(acc[i][j][1]),
                          "+f"(acc[i][j][2]), "+f"(acc[i][j][3])
                        : "r"(af[i][0]), "r"(af[i][1]), "r"(af[i][2]), "r"(af[i][3]),
                          "r"(bf[j][0]), "r"(bf[j][1]));
        }
        if (kt + 1 < NKT) {
            int nxt = cur ^ 1;
#pragma unroll
            for (int it = 0; it < 2; it++) *(float4*)&As[nxt][arow[it]][akc[it]] = tf4(ra[it]);
#pragma unroll
            for (int it = 0; it < NBLD; it++) *(float4*)&Bs[nxt][brow[it]][bnc[it]] = tf4(rb[it]);
        }
        __syncthreads();
    }

#pragma unroll
    for (int j = 0; j < JN; j++) {
        int cb = wn + j*8 + 2*t4;
        float b0 = bias[cb], b1 = bias[cb + 1];
#pragma unroll
        for (int i = 0; i < 2; i++) {
            int r0 = m0 + wm + i*16 + g;
            float v0 = acc[i][j][0] + b0, v1 = acc[i][j][1] + b1;
            float v2 = acc[i][j][2] + b0, v3 = acc[i][j][3] + b1;
            if ((EPI & 1) == 0) {
                v0 = 1.f/(1.f+expf(-v0)); v1 = 1.f/(1.f+expf(-v1));
                v2 = 1.f/(1.f+expf(-v2)); v3 = 1.f/(1.f+expf(-v3));
            } else {
                v0 = tanhf(v0); v1 = tanhf(v1); v2 = tanhf(v2); v3 = tanhf(v3);
            }
            epi_store<EPI>(r0,     cb,     v0);
            epi_store<EPI>(r0,     cb + 1, v1);
            epi_store<EPI>(r0 + 8, cb,     v2);
            epi_store<EPI>(r0 + 8, cb + 1, v3);
        }
    }
}

__global__ void proj_k(const float* __restrict__ pw, const float* __restrict__ pb,
                       float* __restrict__ out, int t) {
    int idx = blockIdx.x * 256 + threadIdx.x;
    if (idx >= NB) return;
    int n = idx >> 7, b = idx & 127;
    float s = pb[0];
    const float* hh = &g_h1[idx * UNITS];
#pragma unroll
    for (int k = 0; k < UNITS; k++) s += hh[k] * pw[k];
    out[(b * T_OUTS + t) * N_NODES + n] = s;
    g_XG0[idx*LDA0] = s;
    g_XC0[idx*LDA0] = s;
}

// ---------------- host orchestration ----------------
#define SMEMF0 (512*36*4)
#define SMEMF1 (512*32*4)

static void launch_gconv(int lay, int sel) {
    if (lay == 0) spmm_fused_k<0><<<dim3(256,1,2), 512, SMEMF0>>>(sel);
    else          spmm_fused_k<1><<<dim3(512,1,2), 512, SMEMF1>>>(sel);
}
static void launch_step(const float* bg0, const float* bc0,
                        const float* bg1, const float* bc1) {
    launch_gconv(0, 0);
    gemm_tc<0><<<512, 256>>>(bg0);
    launch_gconv(0, 1);
    gemm_tc<1><<<512, 256>>>(bc0);
    launch_gconv(1, 0);
    gemm_tc<2><<<512, 256>>>(bg1);
    launch_gconv(1, 1);
    gemm_tc<3><<<512, 256>>>(bc1);
}

extern "C" void kernel_launch(void* const* d_in, const int* in_sizes, int n_in,
                              void* d_out, int out_size) {
    const float* hist = (const float*)d_in[0];
    const int*   ei   = (const int*)d_in[1];
    const float* ea   = (const float*)d_in[2];
    const float* W[16];
    for (int i = 0; i < 16; i++) W[i] = (const float*)d_in[3 + i];
    const float* pw = (const float*)d_in[19];
    const float* pb = (const float*)d_in[20];
    float* out = (float*)d_out;

    cudaFuncSetAttribute(spmm_fused_k<0>, cudaFuncAttributeMaxDynamicSharedMemorySize, SMEMF0);
    cudaFuncSetAttribute(spmm_fused_k<1>, cudaFuncAttributeMaxDynamicSharedMemorySize, SMEMF1);

    // --- supports + state setup ---
    zero_setup_k<<<(N_NODES*N_NODES)/256, 256>>>();
    zero_state_k<<<(NB*128)/256, 256>>>();
    scatter_k<<<E_EDGES/256, 256>>>(ei, ea);
    rowinv_k<<<N_NODES, 256>>>();
    colinv_k<<<2, 256>>>();
    count_k<<<(N_NODES*N_NODES)/256, 256>>>();
    scan_k<<<1, 32>>>();
    fill_k<<<(N_NODES*N_NODES)/256, 256>>>();

    // --- permute encoder weights ---
    permW_k<<<(M_DIFF*C0*128 + 255)/256, 256>>>(W[0], 0, C0, SL0, 128);
    permW_k<<<(M_DIFF*C0*64  + 255)/256, 256>>>(W[2], 1, C0, SL0, 64);
    permW_k<<<(M_DIFF*C1*128 + 255)/256, 256>>>(W[4], 2, C1, SL1, 128);
    permW_k<<<(M_DIFF*C1*64  + 255)/256, 256>>>(W[6], 3, C1, SL1, 64);

    // --- encoder ---
    for (int t = 0; t < T_INS; t++) {
        in_k<<<(NB + 255)/256, 256>>>(hist + (size_t)t * NB);
        launch_step(W[1], W[3], W[5], W[7]);
    }

    // --- permute decoder weights ---
    permW_k<<<(M_DIFF*C0*128 + 255)/256, 256>>>(W[8],  0, C0, SL0, 128);
    permW_k<<<(M_DIFF*C0*64  + 255)/256, 256>>>(W[10], 1, C0, SL0, 64);
    permW_k<<<(M_DIFF*C1*128 + 255)/256, 256>>>(W[12], 2, C1, SL1, 128);
    permW_k<<<(M_DIFF*C1*64  + 255)/256, 256>>>(W[14], 3, C1, SL1, 64);

    // --- decoder ---
    zgo_k<<<(NB + 255)/256, 256>>>();
    for (int t = 0; t < T_OUTS; t++) {
        launch_step(W[9], W[11], W[13], W[15]);
        proj_k<<<(NB + 255)/256, 256>>>(pw, pb, out, t);
    }
}